// round 15
// baseline (speedup 1.0000x reference)
#include <cuda_runtime.h>
#include <cuda_fp16.h>
#include <cstdint>

// ---------------------------------------------------------------------------
// WideHyperBasicBlock via mma.sync (HMMA). conv3x3 = 9 shifted GEMMs,
// fp16 in / fp32 accum. Activations channel-last actT[b][y][x][ci].
// R15 = R14 + both convs FUSED into one launch with per-sample flags:
//   group g: 64 conv1 tiles of sample g  +  64 conv2 tiles of sample g-2.
//   conv1 end: red.release.gpu.add(g_done[b]); conv2 start: acquire-spin
//   until g_done[b]==64. Flags reset by aux_fused each replay.
// Conv CTA: 128co x 128px (2 rows), 256 thr, 8 warps, warp = 64co x 32px;
// 3-deep A ring + 2-deep B ring (B reused across kx), 1 sync/stage.
// ---------------------------------------------------------------------------

#define NB 32
#define NC 256
#define YT 66
#define XT 66
#define ATSZ (NB * YT * XT * NC)
#define GWSZ (NB * 9 * NC * NC)

__device__ __half g_at1[ATSZ];
__device__ __half g_at2[ATSZ];
__device__ __half g_gw1[GWSZ];
__device__ __half g_gw2[GWSZ];
__device__ int    g_done[NB];

__device__ __forceinline__ uint32_t smem_u32(const void* p) {
    uint32_t a;
    asm("{ .reg .u64 t; cvta.to.shared.u64 t, %1; cvt.u32.u64 %0, t; }"
        : "=r"(a) : "l"(p));
    return a;
}
#define SWZ(o) ((o) ^ (((o) >> 3) & 0x70))
#define CPA16(dst, src) \
    asm volatile("cp.async.cg.shared.global [%0], [%1], 16;" :: "r"(dst), "l"(src) : "memory")

__device__ __forceinline__ uint4 pack8h(const __half* h) {
    union { uint4 u; __half2 h2[4]; } r;
    r.h2[0] = __halves2half2(h[0], h[1]);
    r.h2[1] = __halves2half2(h[2], h[3]);
    r.h2[2] = __halves2half2(h[4], h[5]);
    r.h2[3] = __halves2half2(h[6], h[7]);
    return r.u;
}

// --------------------------- fused aux kernel ------------------------------
#define WGEN_BLKS 2304
#define BNT_BLKS  2048
#define ZB_BLKS   65

__global__ __launch_bounds__(256)
void aux_fused(const float* __restrict__ w1, const float* __restrict__ bw1,
               const float* __restrict__ w2, const float* __restrict__ bw2,
               const float* __restrict__ hv,
               __half* __restrict__ gwa, __half* __restrict__ gwb,
               const float* __restrict__ x,
               const float* __restrict__ g, const float* __restrict__ be,
               const float* __restrict__ m, const float* __restrict__ v,
               __half* __restrict__ at1, __half* __restrict__ at2)
{
    __shared__ __half sT[64 * 258];
    __shared__ float sInv[256], sBias[256];
    const int blk = blockIdx.x;
    const int t = threadIdx.x;

    if (blk < WGEN_BLKS) {
        int gid = blk * 256 + t;
        const int per = 9 * 32768;
        int lay = gid >= per;
        int tt = lay ? (gid - per) : gid;
        const float* w  = lay ? w2  : w1;
        const float* bw = lay ? bw2 : bw1;
        __half* gw = lay ? gwb : gwa;
        int k = tt >> 15;
        int j = tt & 32767;
        int mm = j * 2;
        float w0 = w[mm * 9 + k],  w1v = w[(mm + 1) * 9 + k];
        float b0 = bw[mm * 9 + k], b1v = bw[(mm + 1) * 9 + k];
        __half* dst = gw + (k << 16) + mm;
#pragma unroll 4
        for (int b = 0; b < 32; b++) {
            float h = 0.5f + hv[b] * (1.0f / 64.0f);
            __half2 r = __floats2half2_rn(fmaf(h, w0, b0), fmaf(h, w1v, b1v));
            *(__half2*)(dst + (size_t)b * (9 * 65536)) = r;
        }
    } else if (blk < WGEN_BLKS + BNT_BLKS) {
        const int bb = blk - WGEN_BLKS;
        const int y = bb & 63, b = bb >> 6;
        {
            float inv = g[t] * rsqrtf(v[t] + 1e-5f);
            sInv[t]  = inv;
            sBias[t] = be[t] - m[t] * inv;
        }
        __syncthreads();
        const int xcol = t & 63, cg = t >> 6;
#pragma unroll 4
        for (int i = 0; i < 64; i++) {
            int c = i * 4 + cg;
            float xv = x[(((size_t)(b * 256 + c)) << 12) + (y << 6) + xcol];
            sT[xcol * 258 + c] = __float2half(fmaxf(fmaf(xv, sInv[c], sBias[c]), 0.0f));
        }
        __syncthreads();
#pragma unroll
        for (int it = 0; it < 8; it++) {
            int id = it * 256 + t;
            int xx = id >> 5, gg = id & 31;
            const uint32_t* sp = (const uint32_t*)(sT + xx * 258 + gg * 8);
            uint4 val = {sp[0], sp[1], sp[2], sp[3]};
            *(uint4*)(at1 + (((size_t)b * YT + y + 1) * XT + (xx + 1)) * NC + gg * 8) = val;
        }
    } else {
        // zero borders of both buffers + reset per-sample flags
        int zb = blk - WGEN_BLKS - BNT_BLKS;
        if (zb == 0 && t < NB) g_done[t] = 0;
        int gid = zb * 256 + t;
        const int per = 32 * 8320;
        if (gid >= 2 * per) return;
        __half* buf = (gid < per) ? at1 : at2;
        int r0 = gid % per;
        int b = r0 / 8320, r = r0 % 8320;
        int y, xx, gg;
        if (r < 4224) {
            y = (r < 2112) ? 0 : 65;
            int rr = r % 2112;
            xx = rr >> 5; gg = rr & 31;
        } else {
            int rr = r - 4224;
            y = 1 + (rr >> 6);
            int rem = rr & 63;
            xx = (rem < 32) ? 0 : 65; gg = rem & 31;
        }
        uint4 z = {0, 0, 0, 0};
        *(uint4*)(buf + (((size_t)b * YT + y) * XT + xx) * NC + gg * 8) = z;
    }
}

// --------------------------- fused conv kernel -----------------------------
// grid (128, 34). group g = blockIdx.y:
//   x <  64 : conv1 tile x of sample g      (skip if g >= 32)
//   x >= 64 : conv2 tile x-64 of sample g-2 (skip if g <  2)
// tile: y0 = (tile & 31)*2, co0 = (tile >> 5)*128.
#define B_RING   49152
#define SMEM_BYTES 84992

__global__ __launch_bounds__(256, 2)
void conv_fused(const __half* __restrict__ at1, const __half* __restrict__ at2,
                const __half* __restrict__ gw1, const __half* __restrict__ gw2,
                const float* __restrict__ bn_g, const float* __restrict__ bn_b,
                const float* __restrict__ bn_m, const float* __restrict__ bn_v,
                const float* __restrict__ xres, float* __restrict__ out)
{
    extern __shared__ __align__(1024) char smem[];
    __shared__ float sSc[128], sBi[128];
    const int tid  = threadIdx.x;

    int mode, b, tile;
    {
        const int gg = blockIdx.y, xb = blockIdx.x;
        if (xb < 64) {
            if (gg >= 32) return;
            mode = 0; b = gg; tile = xb;
        } else {
            if (gg < 2) return;
            mode = 1; b = gg - 2; tile = xb - 64;
        }
    }
    const int y0  = (tile & 31) * 2;
    const int co0 = (tile >> 5) * 128;

    const __half* at = (mode == 0) ? at1 : at2;
    const __half* gw = (mode == 0) ? gw1 : gw2;
    __half* oT = g_at2;

    const uint32_t sb = smem_u32(smem);
    const int wid  = tid >> 5, lane = tid & 31;
    const int wm   = wid & 1;
    const int wn   = wid >> 1;
    const int jblk = wn >> 1;
    const int nbase = (wn & 1) * 32;
    const int lr  = lane & 15;
    const int lhi = (lane >> 4) & 1;

    if (mode == 0 && tid < 128) {
        int co = co0 + tid;
        float inv = bn_g[co] * rsqrtf(bn_v[co] + 1e-5f);
        sSc[tid] = inv;
        sBi[tid] = bn_b[co] - bn_m[co] * inv;
    }

    if (mode == 1) {
        // wait until all 64 conv1 tiles of sample b have published at2
        if (tid == 0) {
            int v;
            do {
                asm volatile("ld.acquire.gpu.global.s32 %0, [%1];"
                             : "=r"(v) : "l"(g_done + b) : "memory");
                if (v < 64) __nanosleep(200);
            } while (v < 64);
        }
        __syncthreads();
    }

    float acc[4][4][4];
#pragma unroll
    for (int i = 0; i < 4; i++)
#pragma unroll
        for (int j = 0; j < 4; j++)
#pragma unroll
            for (int k = 0; k < 4; k++) acc[i][j][k] = 0.0f;

    auto load_stage = [&](int s) {
        const int blk = s / 3, kx = s % 3;
        const int ky  = blk >> 2;
        const int cic = (blk & 3) << 6;
        const int tap = ky * 3 + kx;
        const uint32_t aBase = sb + (uint32_t)(s % 3) * 16384;
        const __half* gsrcA = gw + ((size_t)(b * 9 + tap) * 256 + co0) * 256 + cic;
#pragma unroll
        for (int i = tid; i < 1024; i += 256) {
            int row = i >> 3, g = i & 7;
            CPA16(aBase + SWZ(row * 128 + g * 16),
                  (const char*)(gsrcA + row * 256) + g * 16);
        }
        if (kx == 0) {
            const uint32_t bBase = sb + B_RING + (uint32_t)(blk & 1) * 17408;
            for (int i = tid; i < 1056; i += 256) {
                int j  = (i >= 528) ? 1 : 0;
                int r2 = i - j * 528;
                int r = r2 >> 3, g = r2 & 7;
                const __half* src = at +
                    (((size_t)b * YT + (y0 + j + ky)) * XT + r) * NC + cic + g * 8;
                CPA16(bBase + j * 8704 + SWZ(r * 128 + g * 16), (const char*)src);
            }
        }
        asm volatile("cp.async.commit_group;" ::: "memory");
    };

    load_stage(0);
    load_stage(1);

    for (int s = 0; s < 36; s++) {
        if (s == 35) asm volatile("cp.async.wait_group 0;" ::: "memory");
        else         asm volatile("cp.async.wait_group 1;" ::: "memory");
        __syncthreads();

        if (s + 2 < 36) load_stage(s + 2);

        const int blk = s / 3, kx = s % 3;
        const uint32_t sA  = sb + (uint32_t)(s % 3) * 16384;
        const uint32_t sBj = sb + B_RING + (uint32_t)(blk & 1) * 17408 + jblk * 8704;

#pragma unroll
        for (int ki = 0; ki < 4; ki++) {
            uint32_t a[4][4];
#pragma unroll
            for (int mi = 0; mi < 4; mi++) {
                uint32_t addr = sA + SWZ((wm * 64 + mi * 16 + lr) * 128 +
                                         ki * 32 + lhi * 16);
                asm volatile("ldmatrix.sync.aligned.m8n8.x4.shared.b16 {%0,%1,%2,%3}, [%4];"
                             : "=r"(a[mi][0]), "=r"(a[mi][1]), "=r"(a[mi][2]), "=r"(a[mi][3])
                             : "r"(addr));
            }
            uint32_t bm[2][4];
#pragma unroll
            for (int nt = 0; nt < 2; nt++) {
                uint32_t row = nbase + nt * 16 + (lane & 7) + lhi * 8 + kx;
                uint32_t addr = sBj + SWZ(row * 128 + ki * 32 + ((lane >> 3) & 1) * 16);
                asm volatile("ldmatrix.sync.aligned.m8n8.x4.shared.b16 {%0,%1,%2,%3}, [%4];"
                             : "=r"(bm[nt][0]), "=r"(bm[nt][1]), "=r"(bm[nt][2]), "=r"(bm[nt][3])
                             : "r"(addr));
            }
#pragma unroll
            for (int mi = 0; mi < 4; mi++)
#pragma unroll
                for (int ni = 0; ni < 4; ni++) {
                    uint32_t b0 = bm[ni >> 1][(ni & 1) * 2];
                    uint32_t b1 = bm[ni >> 1][(ni & 1) * 2 + 1];
                    asm volatile(
                        "mma.sync.aligned.m16n8k16.row.col.f32.f16.f16.f32 "
                        "{%0,%1,%2,%3}, {%4,%5,%6,%7}, {%8,%9}, {%0,%1,%2,%3};"
                        : "+f"(acc[mi][ni][0]), "+f"(acc[mi][ni][1]),
                          "+f"(acc[mi][ni][2]), "+f"(acc[mi][ni][3])
                        : "r"(a[mi][0]), "r"(a[mi][1]), "r"(a[mi][2]), "r"(a[mi][3]),
                          "r"(b0), "r"(b1));
                }
        }
    }

    __syncthreads();

    if (mode == 0) {
        float* sT = (float*)smem;
#pragma unroll
        for (int mi = 0; mi < 4; mi++)
#pragma unroll
            for (int h = 0; h < 2; h++) {
                const int co = wm * 64 + mi * 16 + (lane >> 2) + h * 8;
#pragma unroll
                for (int ni = 0; ni < 4; ni++) {
                    const int px = wn * 32 + ni * 8 + (lane & 3) * 2;
                    sT[px * 136 + co]       = acc[mi][ni][h * 2];
                    sT[(px + 1) * 136 + co] = acc[mi][ni][h * 2 + 1];
                }
            }
        __syncthreads();
#pragma unroll
        for (int it = 0; it < 8; it++) {
            const int id = it * 256 + tid;
            const int g = id & 15, xx = (id >> 4) & 63, j = id >> 10;
            const float* rp = sT + (j * 64 + xx) * 136 + g * 8;
            float4 va = *(const float4*)rp;
            float4 vb = *(const float4*)(rp + 4);
            float vv[8] = {va.x, va.y, va.z, va.w, vb.x, vb.y, vb.z, vb.w};
            __half hh[8];
#pragma unroll
            for (int i = 0; i < 8; i++)
                hh[i] = __float2half(
                    fmaxf(fmaf(vv[i], sSc[g * 8 + i], sBi[g * 8 + i]), 0.0f));
            *(uint4*)(oT + (((size_t)b * YT + (y0 + j + 1)) * XT + (xx + 1)) * NC +
                      co0 + g * 8) = pack8h(hh);
        }
        // publish: all stores of this tile done -> bump sample counter
        __syncthreads();
        if (tid == 0)
            asm volatile("red.release.gpu.global.add.s32 [%0], %1;"
                         :: "l"(g_done + b), "r"(1) : "memory");
    } else {
        float* sAcc = (float*)smem;
#pragma unroll
        for (int mi = 0; mi < 4; mi++)
#pragma unroll
            for (int h = 0; h < 2; h++) {
                const int co = wm * 64 + mi * 16 + (lane >> 2) + h * 8;
#pragma unroll
                for (int ni = 0; ni < 4; ni++) {
                    const int px = wn * 32 + ni * 8 + (lane & 3) * 2;
                    sAcc[co * 132 + px]     = acc[mi][ni][h * 2];
                    sAcc[co * 132 + px + 1] = acc[mi][ni][h * 2 + 1];
                }
            }
        __syncthreads();
#pragma unroll
        for (int it = 0; it < 8; it++) {
            const int t2 = it * 256 + tid;
            const int co = t2 >> 4;
            const int ch = t2 & 15;
            const int j  = ch >> 3;
            const int xl = (ch & 7) * 8;
            const float* rowp = sAcc + co * 132 + j * 64;
            float4 va = *(const float4*)(rowp + xl);
            float4 vb = *(const float4*)(rowp + xl + 4);
            const int gb = ((b * 256 + co0 + co) << 12) + ((y0 + j) << 6) + xl;
            float4 x0 = *(const float4*)(xres + gb);
            float4 x1 = *(const float4*)(xres + gb + 4);
            float4 r0, r1;
            r0.x = va.x + x0.x; r0.y = va.y + x0.y;
            r0.z = va.z + x0.z; r0.w = va.w + x0.w;
            r1.x = vb.x + x1.x; r1.y = vb.y + x1.y;
            r1.z = vb.z + x1.z; r1.w = vb.w + x1.w;
            *(float4*)(out + gb)     = r0;
            *(float4*)(out + gb + 4) = r1;
        }
    }
}

// ------------------------------- launcher ----------------------------------
extern "C" void kernel_launch(void* const* d_in, const int* in_sizes, int n_in,
                              void* d_out, int out_size)
{
    const float* x    = (const float*)d_in[0];
    const float* h_in = (const float*)d_in[1];
    const float* g1   = (const float*)d_in[2];
    const float* be1  = (const float*)d_in[3];
    const float* m1   = (const float*)d_in[4];
    const float* v1   = (const float*)d_in[5];
    const float* w1   = (const float*)d_in[6];
    const float* b1   = (const float*)d_in[7];
    const float* g2   = (const float*)d_in[8];
    const float* be2  = (const float*)d_in[9];
    const float* m2   = (const float*)d_in[10];
    const float* v2   = (const float*)d_in[11];
    const float* w2   = (const float*)d_in[12];
    const float* b2   = (const float*)d_in[13];
    float* out = (float*)d_out;

    void *p1, *p2, *pg1, *pg2;
    cudaGetSymbolAddress(&p1, g_at1);
    cudaGetSymbolAddress(&p2, g_at2);
    cudaGetSymbolAddress(&pg1, g_gw1);
    cudaGetSymbolAddress(&pg2, g_gw2);
    __half* at1 = (__half*)p1;
    __half* at2 = (__half*)p2;
    __half* gw1 = (__half*)pg1;
    __half* gw2 = (__half*)pg2;

    cudaFuncSetAttribute(conv_fused, cudaFuncAttributeMaxDynamicSharedMemorySize, SMEM_BYTES);

    aux_fused<<<WGEN_BLKS + BNT_BLKS + ZB_BLKS, 256>>>(
        w1, b1, w2, b2, h_in, gw1, gw2,
        x, g1, be1, m1, v1, at1, at2);

    dim3 cg(128, 34);
    conv_fused<<<cg, 256, SMEM_BYTES>>>(at1, at2, gw1, gw2,
                                        g2, be2, m2, v2, x, out);
}

// round 16
// speedup vs baseline: 1.0591x; 1.0591x over previous
#include <cuda_runtime.h>
#include <cuda_fp16.h>
#include <cstdint>

// ---------------------------------------------------------------------------
// WideHyperBasicBlock via mma.sync (HMMA). conv3x3 = 9 shifted GEMMs,
// fp16 in / fp32 accum. Activations channel-last actT[b][y][x][ci]
// (66x66 padded, 512B rows); shifts are row offsets -> one padded copy.
// B window loaded once per (ky, ci-chunk) block, reused by all 3 kx taps.
// R16 = R14 + PDL overlap: conv1 triggers launch_dependents after its
// prologue; conv2 prefetches its weight tiles (A0,A1) BEFORE
// griddepcontrol.wait, so conv1's tail wave is filled with conv2 weight
// staging and the kernel-boundary launch gap disappears.
// Conv CTA: 128co x 128px (2 rows), 256 thr, 8 warps, warp = 64co x 32px;
// 3-deep A ring + 2-deep B ring, 1 sync/stage.
// ---------------------------------------------------------------------------

#define NB 32
#define NC 256
#define YT 66
#define XT 66
#define ATSZ (NB * YT * XT * NC)
#define GWSZ (NB * 9 * NC * NC)

__device__ __half g_at1[ATSZ];
__device__ __half g_at2[ATSZ];
__device__ __half g_gw1[GWSZ];
__device__ __half g_gw2[GWSZ];

__device__ __forceinline__ uint32_t smem_u32(const void* p) {
    uint32_t a;
    asm("{ .reg .u64 t; cvta.to.shared.u64 t, %1; cvt.u32.u64 %0, t; }"
        : "=r"(a) : "l"(p));
    return a;
}
#define SWZ(o) ((o) ^ (((o) >> 3) & 0x70))
#define CPA16(dst, src) \
    asm volatile("cp.async.cg.shared.global [%0], [%1], 16;" :: "r"(dst), "l"(src) : "memory")

__device__ __forceinline__ uint4 pack8h(const __half* h) {
    union { uint4 u; __half2 h2[4]; } r;
    r.h2[0] = __halves2half2(h[0], h[1]);
    r.h2[1] = __halves2half2(h[2], h[3]);
    r.h2[2] = __halves2half2(h[4], h[5]);
    r.h2[3] = __halves2half2(h[6], h[7]);
    return r.u;
}

// --------------------------- fused aux kernel ------------------------------
#define WGEN_BLKS 2304
#define BNT_BLKS  2048
#define ZB_BLKS   65

__global__ __launch_bounds__(256)
void aux_fused(const float* __restrict__ w1, const float* __restrict__ bw1,
               const float* __restrict__ w2, const float* __restrict__ bw2,
               const float* __restrict__ hv,
               __half* __restrict__ gwa, __half* __restrict__ gwb,
               const float* __restrict__ x,
               const float* __restrict__ g, const float* __restrict__ be,
               const float* __restrict__ m, const float* __restrict__ v,
               __half* __restrict__ at1, __half* __restrict__ at2)
{
    __shared__ __half sT[64 * 258];
    __shared__ float sInv[256], sBias[256];
    const int blk = blockIdx.x;
    const int t = threadIdx.x;

    if (blk < WGEN_BLKS) {
        int gid = blk * 256 + t;
        const int per = 9 * 32768;
        int lay = gid >= per;
        int tt = lay ? (gid - per) : gid;
        const float* w  = lay ? w2  : w1;
        const float* bw = lay ? bw2 : bw1;
        __half* gw = lay ? gwb : gwa;
        int k = tt >> 15;
        int j = tt & 32767;
        int mm = j * 2;
        float w0 = w[mm * 9 + k],  w1v = w[(mm + 1) * 9 + k];
        float b0 = bw[mm * 9 + k], b1v = bw[(mm + 1) * 9 + k];
        __half* dst = gw + (k << 16) + mm;
#pragma unroll 4
        for (int b = 0; b < 32; b++) {
            float h = 0.5f + hv[b] * (1.0f / 64.0f);
            __half2 r = __floats2half2_rn(fmaf(h, w0, b0), fmaf(h, w1v, b1v));
            *(__half2*)(dst + (size_t)b * (9 * 65536)) = r;
        }
    } else if (blk < WGEN_BLKS + BNT_BLKS) {
        const int bb = blk - WGEN_BLKS;
        const int y = bb & 63, b = bb >> 6;
        {
            float inv = g[t] * rsqrtf(v[t] + 1e-5f);
            sInv[t]  = inv;
            sBias[t] = be[t] - m[t] * inv;
        }
        __syncthreads();
        const int xcol = t & 63, cg = t >> 6;
#pragma unroll 4
        for (int i = 0; i < 64; i++) {
            int c = i * 4 + cg;
            float xv = x[(((size_t)(b * 256 + c)) << 12) + (y << 6) + xcol];
            sT[xcol * 258 + c] = __float2half(fmaxf(fmaf(xv, sInv[c], sBias[c]), 0.0f));
        }
        __syncthreads();
#pragma unroll
        for (int it = 0; it < 8; it++) {
            int id = it * 256 + t;
            int xx = id >> 5, gg = id & 31;
            const uint32_t* sp = (const uint32_t*)(sT + xx * 258 + gg * 8);
            uint4 val = {sp[0], sp[1], sp[2], sp[3]};
            *(uint4*)(at1 + (((size_t)b * YT + y + 1) * XT + (xx + 1)) * NC + gg * 8) = val;
        }
    } else {
        int gid = (blk - WGEN_BLKS - BNT_BLKS) * 256 + t;
        const int per = 32 * 8320;
        if (gid >= 2 * per) return;
        __half* buf = (gid < per) ? at1 : at2;
        int r0 = gid % per;
        int b = r0 / 8320, r = r0 % 8320;
        int y, xx, gg;
        if (r < 4224) {
            y = (r < 2112) ? 0 : 65;
            int rr = r % 2112;
            xx = rr >> 5; gg = rr & 31;
        } else {
            int rr = r - 4224;
            y = 1 + (rr >> 6);
            int rem = rr & 63;
            xx = (rem < 32) ? 0 : 65; gg = rem & 31;
        }
        uint4 z = {0, 0, 0, 0};
        *(uint4*)(buf + (((size_t)b * YT + y) * XT + xx) * NC + gg * 8) = z;
    }
}

// --------------------------- main conv kernel ------------------------------
// Stage s (0..35): block = s/3 (ky = block>>2, cic = (block&3)*64), kx = s%3.
// A ring: 3 x 16384 @ sb;  B ring: 2 x 17408 @ sb+49152.
#define B_RING   49152
#define SMEM_BYTES 84992

template <int MODE>
__global__ __launch_bounds__(256, 2)
void conv_mma(const __half* __restrict__ at, const __half* __restrict__ gw,
              const float* __restrict__ bn_g, const float* __restrict__ bn_b,
              const float* __restrict__ bn_m, const float* __restrict__ bn_v,
              const float* __restrict__ xres,
              __half* __restrict__ oT, float* __restrict__ out)
{
    extern __shared__ __align__(1024) char smem[];
    __shared__ float sSc[128], sBi[128];
    const uint32_t sb = smem_u32(smem);
    const int tid  = threadIdx.x;
    const int wid  = tid >> 5, lane = tid & 31;
    const int wm   = wid & 1;
    const int wn   = wid >> 1;
    const int jblk = wn >> 1;
    const int nbase = (wn & 1) * 32;

    const int y0  = blockIdx.x * 2;
    const int co0 = blockIdx.y * 128;
    const int b   = blockIdx.z;

    const int lr  = lane & 15;
    const int lhi = (lane >> 4) & 1;

    if (MODE == 0 && tid < 128) {
        int co = co0 + tid;
        float inv = bn_g[co] * rsqrtf(bn_v[co] + 1e-5f);
        sSc[tid] = inv;
        sBi[tid] = bn_b[co] - bn_m[co] * inv;
    }

    float acc[4][4][4];
#pragma unroll
    for (int i = 0; i < 4; i++)
#pragma unroll
        for (int j = 0; j < 4; j++)
#pragma unroll
            for (int k = 0; k < 4; k++) acc[i][j][k] = 0.0f;

    // A part of stage s (weights — independent of the producer conv)
    auto load_A = [&](int s) {
        const int blk = s / 3, kx = s % 3;
        const int tap = (blk >> 2) * 3 + kx;
        const int cic = (blk & 3) << 6;
        const uint32_t aBase = sb + (uint32_t)(s % 3) * 16384;
        const __half* gsrcA = gw + ((size_t)(b * 9 + tap) * 256 + co0) * 256 + cic;
#pragma unroll
        for (int i = tid; i < 1024; i += 256) {
            int row = i >> 3, g = i & 7;
            CPA16(aBase + SWZ(row * 128 + g * 16),
                  (const char*)(gsrcA + row * 256) + g * 16);
        }
    };
    // B part of block blk (activations — depends on the producer conv)
    auto load_B = [&](int blk) {
        const int ky  = blk >> 2;
        const int cic = (blk & 3) << 6;
        const uint32_t bBase = sb + B_RING + (uint32_t)(blk & 1) * 17408;
        for (int i = tid; i < 1056; i += 256) {
            int j  = (i >= 528) ? 1 : 0;
            int r2 = i - j * 528;
            int r = r2 >> 3, g = r2 & 7;
            const __half* src = at +
                (((size_t)b * YT + (y0 + j + ky)) * XT + r) * NC + cic + g * 8;
            CPA16(bBase + j * 8704 + SWZ(r * 128 + g * 16), (const char*)src);
        }
    };
    auto load_stage = [&](int s) {
        load_A(s);
        if (s % 3 == 0) load_B(s / 3);
        asm volatile("cp.async.commit_group;" ::: "memory");
    };

    if (MODE == 0) {
        load_stage(0);
        load_stage(1);
        // let the dependent (conv2) grid start tail-filling freed SMs
        asm volatile("griddepcontrol.launch_dependents;");
    } else {
        // prefetch weights for stages 0,1 BEFORE waiting on producer grid
        load_A(0);
        load_A(1);
        asm volatile("griddepcontrol.wait;" ::: "memory");
        load_B(0);
        asm volatile("cp.async.commit_group;" ::: "memory");  // G0 = A0+A1+B0
        asm volatile("cp.async.commit_group;" ::: "memory");  // G1 = empty
    }

    for (int s = 0; s < 36; s++) {
        if (s == 35) asm volatile("cp.async.wait_group 0;" ::: "memory");
        else         asm volatile("cp.async.wait_group 1;" ::: "memory");
        __syncthreads();

        if (s + 2 < 36) load_stage(s + 2);

        const int blk = s / 3, kx = s % 3;
        const uint32_t sA  = sb + (uint32_t)(s % 3) * 16384;
        const uint32_t sBj = sb + B_RING + (uint32_t)(blk & 1) * 17408 + jblk * 8704;

#pragma unroll
        for (int ki = 0; ki < 4; ki++) {
            uint32_t a[4][4];
#pragma unroll
            for (int mi = 0; mi < 4; mi++) {
                uint32_t addr = sA + SWZ((wm * 64 + mi * 16 + lr) * 128 +
                                         ki * 32 + lhi * 16);
                asm volatile("ldmatrix.sync.aligned.m8n8.x4.shared.b16 {%0,%1,%2,%3}, [%4];"
                             : "=r"(a[mi][0]), "=r"(a[mi][1]), "=r"(a[mi][2]), "=r"(a[mi][3])
                             : "r"(addr));
            }
            uint32_t bm[2][4];
#pragma unroll
            for (int nt = 0; nt < 2; nt++) {
                uint32_t row = nbase + nt * 16 + (lane & 7) + lhi * 8 + kx;
                uint32_t addr = sBj + SWZ(row * 128 + ki * 32 + ((lane >> 3) & 1) * 16);
                asm volatile("ldmatrix.sync.aligned.m8n8.x4.shared.b16 {%0,%1,%2,%3}, [%4];"
                             : "=r"(bm[nt][0]), "=r"(bm[nt][1]), "=r"(bm[nt][2]), "=r"(bm[nt][3])
                             : "r"(addr));
            }
#pragma unroll
            for (int mi = 0; mi < 4; mi++)
#pragma unroll
                for (int ni = 0; ni < 4; ni++) {
                    uint32_t b0 = bm[ni >> 1][(ni & 1) * 2];
                    uint32_t b1 = bm[ni >> 1][(ni & 1) * 2 + 1];
                    asm volatile(
                        "mma.sync.aligned.m16n8k16.row.col.f32.f16.f16.f32 "
                        "{%0,%1,%2,%3}, {%4,%5,%6,%7}, {%8,%9}, {%0,%1,%2,%3};"
                        : "+f"(acc[mi][ni][0]), "+f"(acc[mi][ni][1]),
                          "+f"(acc[mi][ni][2]), "+f"(acc[mi][ni][3])
                        : "r"(a[mi][0]), "r"(a[mi][1]), "r"(a[mi][2]), "r"(a[mi][3]),
                          "r"(b0), "r"(b1));
                }
        }
    }

    __syncthreads();

    if (MODE == 0) {
        float* sT = (float*)smem;
#pragma unroll
        for (int mi = 0; mi < 4; mi++)
#pragma unroll
            for (int h = 0; h < 2; h++) {
                const int co = wm * 64 + mi * 16 + (lane >> 2) + h * 8;
#pragma unroll
                for (int ni = 0; ni < 4; ni++) {
                    const int px = wn * 32 + ni * 8 + (lane & 3) * 2;
                    sT[px * 136 + co]       = acc[mi][ni][h * 2];
                    sT[(px + 1) * 136 + co] = acc[mi][ni][h * 2 + 1];
                }
            }
        __syncthreads();
#pragma unroll
        for (int it = 0; it < 8; it++) {
            const int id = it * 256 + tid;
            const int g = id & 15, xx = (id >> 4) & 63, j = id >> 10;
            const float* rp = sT + (j * 64 + xx) * 136 + g * 8;
            float4 va = *(const float4*)rp;
            float4 vb = *(const float4*)(rp + 4);
            float vv[8] = {va.x, va.y, va.z, va.w, vb.x, vb.y, vb.z, vb.w};
            __half hh[8];
#pragma unroll
            for (int i = 0; i < 8; i++)
                hh[i] = __float2half(
                    fmaxf(fmaf(vv[i], sSc[g * 8 + i], sBi[g * 8 + i]), 0.0f));
            *(uint4*)(oT + (((size_t)b * YT + (y0 + j + 1)) * XT + (xx + 1)) * NC +
                      co0 + g * 8) = pack8h(hh);
        }
    } else {
        float* sAcc = (float*)smem;
#pragma unroll
        for (int mi = 0; mi < 4; mi++)
#pragma unroll
            for (int h = 0; h < 2; h++) {
                const int co = wm * 64 + mi * 16 + (lane >> 2) + h * 8;
#pragma unroll
                for (int ni = 0; ni < 4; ni++) {
                    const int px = wn * 32 + ni * 8 + (lane & 3) * 2;
                    sAcc[co * 132 + px]     = acc[mi][ni][h * 2];
                    sAcc[co * 132 + px + 1] = acc[mi][ni][h * 2 + 1];
                }
            }
        __syncthreads();
#pragma unroll
        for (int it = 0; it < 8; it++) {
            const int t2 = it * 256 + tid;
            const int co = t2 >> 4;
            const int ch = t2 & 15;
            const int j  = ch >> 3;
            const int xl = (ch & 7) * 8;
            const float* rowp = sAcc + co * 132 + j * 64;
            float4 va = *(const float4*)(rowp + xl);
            float4 vb = *(const float4*)(rowp + xl + 4);
            const int gb = ((b * 256 + co0 + co) << 12) + ((y0 + j) << 6) + xl;
            float4 x0 = *(const float4*)(xres + gb);
            float4 x1 = *(const float4*)(xres + gb + 4);
            float4 r0, r1;
            r0.x = va.x + x0.x; r0.y = va.y + x0.y;
            r0.z = va.z + x0.z; r0.w = va.w + x0.w;
            r1.x = vb.x + x1.x; r1.y = vb.y + x1.y;
            r1.z = vb.z + x1.z; r1.w = vb.w + x1.w;
            *(float4*)(out + gb)     = r0;
            *(float4*)(out + gb + 4) = r1;
        }
    }
}

// ------------------------------- launcher ----------------------------------
extern "C" void kernel_launch(void* const* d_in, const int* in_sizes, int n_in,
                              void* d_out, int out_size)
{
    const float* x    = (const float*)d_in[0];
    const float* h_in = (const float*)d_in[1];
    const float* g1   = (const float*)d_in[2];
    const float* be1  = (const float*)d_in[3];
    const float* m1   = (const float*)d_in[4];
    const float* v1   = (const float*)d_in[5];
    const float* w1   = (const float*)d_in[6];
    const float* b1   = (const float*)d_in[7];
    const float* g2   = (const float*)d_in[8];
    const float* be2  = (const float*)d_in[9];
    const float* m2   = (const float*)d_in[10];
    const float* v2   = (const float*)d_in[11];
    const float* w2   = (const float*)d_in[12];
    const float* b2   = (const float*)d_in[13];
    float* out = (float*)d_out;

    void *p1, *p2, *pg1, *pg2;
    cudaGetSymbolAddress(&p1, g_at1);
    cudaGetSymbolAddress(&p2, g_at2);
    cudaGetSymbolAddress(&pg1, g_gw1);
    cudaGetSymbolAddress(&pg2, g_gw2);
    __half* at1 = (__half*)p1;
    __half* at2 = (__half*)p2;
    __half* gw1 = (__half*)pg1;
    __half* gw2 = (__half*)pg2;

    cudaFuncSetAttribute(conv_mma<0>, cudaFuncAttributeMaxDynamicSharedMemorySize, SMEM_BYTES);
    cudaFuncSetAttribute(conv_mma<1>, cudaFuncAttributeMaxDynamicSharedMemorySize, SMEM_BYTES);

    aux_fused<<<WGEN_BLKS + BNT_BLKS + ZB_BLKS, 256>>>(
        w1, b1, w2, b2, h_in, gw1, gw2,
        x, g1, be1, m1, v1, at1, at2);

    dim3 cg(32, 2, NB);
    conv_mma<0><<<cg, 256, SMEM_BYTES>>>(at1, gw1, g2, be2, m2, v2,
                                         nullptr, at2, nullptr);

    // conv2: programmatic dependent launch — overlaps conv1's tail wave
    cudaLaunchConfig_t cfg = {};
    cfg.gridDim = cg;
    cfg.blockDim = dim3(256, 1, 1);
    cfg.dynamicSmemBytes = SMEM_BYTES;
    cfg.stream = 0;
    cudaLaunchAttribute attrs[1];
    attrs[0].id = cudaLaunchAttributeProgrammaticStreamSerialization;
    attrs[0].val.programmaticStreamSerializationAllowed = 1;
    cfg.attrs = attrs;
    cfg.numAttrs = 1;
    cudaLaunchKernelEx(&cfg, conv_mma<1>,
                       (const __half*)at2, (const __half*)gw2,
                       (const float*)nullptr, (const float*)nullptr,
                       (const float*)nullptr, (const float*)nullptr,
                       (const float*)x, (__half*)nullptr, (float*)out);
}

// round 17
// speedup vs baseline: 1.0646x; 1.0052x over previous
#include <cuda_runtime.h>
#include <cuda_fp16.h>
#include <cstdint>

// ---------------------------------------------------------------------------
// WideHyperBasicBlock via mma.sync (HMMA). conv3x3 = 9 shifted GEMMs,
// fp16 in / fp32 accum. Activations channel-last actT[b][y][x][ci].
// R17 = R16 with gw2 generation MOVED INTO conv1's prologue (hidden under
// the tensor pipe; conv2's PDL wait already orders it), aux shrinks to
// gw1+bnT+borders, and PDL pairs aux->conv1 and conv1->conv2.
// Conv CTA: 128co x 128px (2 rows), 256 thr, 8 warps, warp = 64co x 32px;
// 3-deep A ring + 2-deep B ring (B reused across kx), 1 sync/stage.
// ---------------------------------------------------------------------------

#define NB 32
#define NC 256
#define YT 66
#define XT 66
#define ATSZ (NB * YT * XT * NC)
#define GWSZ (NB * 9 * NC * NC)

__device__ __half g_at1[ATSZ];
__device__ __half g_at2[ATSZ];
__device__ __half g_gw1[GWSZ];
__device__ __half g_gw2[GWSZ];

__device__ __forceinline__ uint32_t smem_u32(const void* p) {
    uint32_t a;
    asm("{ .reg .u64 t; cvta.to.shared.u64 t, %1; cvt.u32.u64 %0, t; }"
        : "=r"(a) : "l"(p));
    return a;
}
#define SWZ(o) ((o) ^ (((o) >> 3) & 0x70))
#define CPA16(dst, src) \
    asm volatile("cp.async.cg.shared.global [%0], [%1], 16;" :: "r"(dst), "l"(src) : "memory")

__device__ __forceinline__ uint4 pack8h(const __half* h) {
    union { uint4 u; __half2 h2[4]; } r;
    r.h2[0] = __halves2half2(h[0], h[1]);
    r.h2[1] = __halves2half2(h[2], h[3]);
    r.h2[2] = __halves2half2(h[4], h[5]);
    r.h2[3] = __halves2half2(h[6], h[7]);
    return r.u;
}

// --------------------------- fused aux kernel ------------------------------
// gw1 gen + bn/relu/transpose + borders. (gw2 is generated inside conv1.)
#define WGEN_BLKS 1152
#define BNT_BLKS  2048
#define ZB_BLKS   65

__global__ __launch_bounds__(256)
void aux_fused(const float* __restrict__ w1, const float* __restrict__ bw1,
               const float* __restrict__ hv, __half* __restrict__ gwa,
               const float* __restrict__ x,
               const float* __restrict__ g, const float* __restrict__ be,
               const float* __restrict__ m, const float* __restrict__ v,
               __half* __restrict__ at1, __half* __restrict__ at2)
{
    __shared__ __half sT[64 * 258];
    __shared__ float sInv[256], sBias[256];
    const int blk = blockIdx.x;
    const int t = threadIdx.x;

    if (blk < WGEN_BLKS) {
        int tt = blk * 256 + t;
        int k = tt >> 15;
        int j = tt & 32767;
        int mm = j * 2;
        float w0 = w1[mm * 9 + k],  w1v = w1[(mm + 1) * 9 + k];
        float b0 = bw1[mm * 9 + k], b1v = bw1[(mm + 1) * 9 + k];
        __half* dst = gwa + (k << 16) + mm;
#pragma unroll 4
        for (int b = 0; b < 32; b++) {
            float h = 0.5f + hv[b] * (1.0f / 64.0f);
            __half2 r = __floats2half2_rn(fmaf(h, w0, b0), fmaf(h, w1v, b1v));
            *(__half2*)(dst + (size_t)b * (9 * 65536)) = r;
        }
    } else if (blk < WGEN_BLKS + BNT_BLKS) {
        const int bb = blk - WGEN_BLKS;
        const int y = bb & 63, b = bb >> 6;
        {
            float inv = g[t] * rsqrtf(v[t] + 1e-5f);
            sInv[t]  = inv;
            sBias[t] = be[t] - m[t] * inv;
        }
        __syncthreads();
        const int xcol = t & 63, cg = t >> 6;
#pragma unroll 4
        for (int i = 0; i < 64; i++) {
            int c = i * 4 + cg;
            float xv = x[(((size_t)(b * 256 + c)) << 12) + (y << 6) + xcol];
            sT[xcol * 258 + c] = __float2half(fmaxf(fmaf(xv, sInv[c], sBias[c]), 0.0f));
        }
        __syncthreads();
#pragma unroll
        for (int it = 0; it < 8; it++) {
            int id = it * 256 + t;
            int xx = id >> 5, gg = id & 31;
            const uint32_t* sp = (const uint32_t*)(sT + xx * 258 + gg * 8);
            uint4 val = {sp[0], sp[1], sp[2], sp[3]};
            *(uint4*)(at1 + (((size_t)b * YT + y + 1) * XT + (xx + 1)) * NC + gg * 8) = val;
        }
    } else {
        int gid = (blk - WGEN_BLKS - BNT_BLKS) * 256 + t;
        const int per = 32 * 8320;
        if (gid < 2 * per) {
            __half* buf = (gid < per) ? at1 : at2;
            int r0 = gid % per;
            int b = r0 / 8320, r = r0 % 8320;
            int y, xx, gg;
            if (r < 4224) {
                y = (r < 2112) ? 0 : 65;
                int rr = r % 2112;
                xx = rr >> 5; gg = rr & 31;
            } else {
                int rr = r - 4224;
                y = 1 + (rr >> 6);
                int rem = rr & 63;
                xx = (rem < 32) ? 0 : 65; gg = rem & 31;
            }
            uint4 z = {0, 0, 0, 0};
            *(uint4*)(buf + (((size_t)b * YT + y) * XT + xx) * NC + gg * 8) = z;
        }
    }
    asm volatile("griddepcontrol.launch_dependents;");
}

// --------------------------- main conv kernel ------------------------------
// Stage s (0..35): block = s/3 (ky = block>>2, cic = (block&3)*64), kx = s%3.
// A ring: 3 x 16384 @ sb;  B ring: 2 x 17408 @ sb+49152.
#define B_RING   49152
#define SMEM_BYTES 84992

template <int MODE>
__global__ __launch_bounds__(256, 2)
void conv_mma(const __half* __restrict__ at, const __half* __restrict__ gw,
              const float* __restrict__ bn_g, const float* __restrict__ bn_b,
              const float* __restrict__ bn_m, const float* __restrict__ bn_v,
              const float* __restrict__ xres,
              __half* __restrict__ oT, float* __restrict__ out,
              const float* __restrict__ w2g, const float* __restrict__ bw2g,
              const float* __restrict__ hvv, __half* __restrict__ gw2out)
{
    extern __shared__ __align__(1024) char smem[];
    __shared__ float sSc[128], sBi[128];
    const uint32_t sb = smem_u32(smem);
    const int tid  = threadIdx.x;
    const int wid  = tid >> 5, lane = tid & 31;
    const int wm   = wid & 1;
    const int wn   = wid >> 1;
    const int jblk = wn >> 1;
    const int nbase = (wn & 1) * 32;

    const int y0  = blockIdx.x * 2;
    const int co0 = blockIdx.y * 128;
    const int b   = blockIdx.z;

    const int lr  = lane & 15;
    const int lhi = (lane >> 4) & 1;

    // wait for producer grid (aux for conv1; conv1 for conv2)
    asm volatile("griddepcontrol.wait;" ::: "memory");

    if (MODE == 0 && tid < 128) {
        int co = co0 + tid;
        float inv = bn_g[co] * rsqrtf(bn_v[co] + 1e-5f);
        sSc[tid] = inv;
        sBi[tid] = bn_b[co] - bn_m[co] * inv;
    }

    float acc[4][4][4];
#pragma unroll
    for (int i = 0; i < 4; i++)
#pragma unroll
        for (int j = 0; j < 4; j++)
#pragma unroll
            for (int k = 0; k < 4; k++) acc[i][j][k] = 0.0f;

    auto load_stage = [&](int s) {
        const int blk = s / 3, kx = s % 3;
        const int ky  = blk >> 2;
        const int cic = (blk & 3) << 6;
        const int tap = ky * 3 + kx;
        const uint32_t aBase = sb + (uint32_t)(s % 3) * 16384;
        const __half* gsrcA = gw + ((size_t)(b * 9 + tap) * 256 + co0) * 256 + cic;
#pragma unroll
        for (int i = tid; i < 1024; i += 256) {
            int row = i >> 3, g = i & 7;
            CPA16(aBase + SWZ(row * 128 + g * 16),
                  (const char*)(gsrcA + row * 256) + g * 16);
        }
        if (kx == 0) {
            const uint32_t bBase = sb + B_RING + (uint32_t)(blk & 1) * 17408;
            for (int i = tid; i < 1056; i += 256) {
                int j  = (i >= 528) ? 1 : 0;
                int r2 = i - j * 528;
                int r = r2 >> 3, g = r2 & 7;
                const __half* src = at +
                    (((size_t)b * YT + (y0 + j + ky)) * XT + r) * NC + cic + g * 8;
                CPA16(bBase + j * 8704 + SWZ(r * 128 + g * 16), (const char*)src);
            }
        }
        asm volatile("cp.async.commit_group;" ::: "memory");
    };

    load_stage(0);
    load_stage(1);

    if (MODE == 0) {
        // conv2 may start launching (its wait gates it on our completion)
        asm volatile("griddepcontrol.launch_dependents;");
        // generate this CTA's slice of gw2 under the staging latency shadow
        const int bid = (blockIdx.z * 2 + blockIdx.y) * 32 + blockIdx.x;
        const int item = bid * 256 + tid;
        if (item < 9 * 32768) {
            int k = item >> 15;
            int j = item & 32767;
            int mm = j * 2;
            float w0 = w2g[mm * 9 + k],  w1v = w2g[(mm + 1) * 9 + k];
            float b0 = bw2g[mm * 9 + k], b1v = bw2g[(mm + 1) * 9 + k];
            __half* dst = gw2out + (k << 16) + mm;
#pragma unroll 4
            for (int bb = 0; bb < 32; bb++) {
                float h = 0.5f + hvv[bb] * (1.0f / 64.0f);
                __half2 r = __floats2half2_rn(fmaf(h, w0, b0), fmaf(h, w1v, b1v));
                *(__half2*)(dst + (size_t)bb * (9 * 65536)) = r;
            }
        }
    }

    for (int s = 0; s < 36; s++) {
        if (s == 35) asm volatile("cp.async.wait_group 0;" ::: "memory");
        else         asm volatile("cp.async.wait_group 1;" ::: "memory");
        __syncthreads();

        if (s + 2 < 36) load_stage(s + 2);

        const int blk = s / 3, kx = s % 3;
        const uint32_t sA  = sb + (uint32_t)(s % 3) * 16384;
        const uint32_t sBj = sb + B_RING + (uint32_t)(blk & 1) * 17408 + jblk * 8704;

#pragma unroll
        for (int ki = 0; ki < 4; ki++) {
            uint32_t a[4][4];
#pragma unroll
            for (int mi = 0; mi < 4; mi++) {
                uint32_t addr = sA + SWZ((wm * 64 + mi * 16 + lr) * 128 +
                                         ki * 32 + lhi * 16);
                asm volatile("ldmatrix.sync.aligned.m8n8.x4.shared.b16 {%0,%1,%2,%3}, [%4];"
                             : "=r"(a[mi][0]), "=r"(a[mi][1]), "=r"(a[mi][2]), "=r"(a[mi][3])
                             : "r"(addr));
            }
            uint32_t bm[2][4];
#pragma unroll
            for (int nt = 0; nt < 2; nt++) {
                uint32_t row = nbase + nt * 16 + (lane & 7) + lhi * 8 + kx;
                uint32_t addr = sBj + SWZ(row * 128 + ki * 32 + ((lane >> 3) & 1) * 16);
                asm volatile("ldmatrix.sync.aligned.m8n8.x4.shared.b16 {%0,%1,%2,%3}, [%4];"
                             : "=r"(bm[nt][0]), "=r"(bm[nt][1]), "=r"(bm[nt][2]), "=r"(bm[nt][3])
                             : "r"(addr));
            }
#pragma unroll
            for (int mi = 0; mi < 4; mi++)
#pragma unroll
                for (int ni = 0; ni < 4; ni++) {
                    uint32_t b0 = bm[ni >> 1][(ni & 1) * 2];
                    uint32_t b1 = bm[ni >> 1][(ni & 1) * 2 + 1];
                    asm volatile(
                        "mma.sync.aligned.m16n8k16.row.col.f32.f16.f16.f32 "
                        "{%0,%1,%2,%3}, {%4,%5,%6,%7}, {%8,%9}, {%0,%1,%2,%3};"
                        : "+f"(acc[mi][ni][0]), "+f"(acc[mi][ni][1]),
                          "+f"(acc[mi][ni][2]), "+f"(acc[mi][ni][3])
                        : "r"(a[mi][0]), "r"(a[mi][1]), "r"(a[mi][2]), "r"(a[mi][3]),
                          "r"(b0), "r"(b1));
                }
        }
    }

    __syncthreads();

    if (MODE == 0) {
        float* sT = (float*)smem;
#pragma unroll
        for (int mi = 0; mi < 4; mi++)
#pragma unroll
            for (int h = 0; h < 2; h++) {
                const int co = wm * 64 + mi * 16 + (lane >> 2) + h * 8;
#pragma unroll
                for (int ni = 0; ni < 4; ni++) {
                    const int px = wn * 32 + ni * 8 + (lane & 3) * 2;
                    sT[px * 136 + co]       = acc[mi][ni][h * 2];
                    sT[(px + 1) * 136 + co] = acc[mi][ni][h * 2 + 1];
                }
            }
        __syncthreads();
#pragma unroll
        for (int it = 0; it < 8; it++) {
            const int id = it * 256 + tid;
            const int g = id & 15, xx = (id >> 4) & 63, j = id >> 10;
            const float* rp = sT + (j * 64 + xx) * 136 + g * 8;
            float4 va = *(const float4*)rp;
            float4 vb = *(const float4*)(rp + 4);
            float vv[8] = {va.x, va.y, va.z, va.w, vb.x, vb.y, vb.z, vb.w};
            __half hh[8];
#pragma unroll
            for (int i = 0; i < 8; i++)
                hh[i] = __float2half(
                    fmaxf(fmaf(vv[i], sSc[g * 8 + i], sBi[g * 8 + i]), 0.0f));
            *(uint4*)(oT + (((size_t)b * YT + (y0 + j + 1)) * XT + (xx + 1)) * NC +
                      co0 + g * 8) = pack8h(hh);
        }
    } else {
        float* sAcc = (float*)smem;
#pragma unroll
        for (int mi = 0; mi < 4; mi++)
#pragma unroll
            for (int h = 0; h < 2; h++) {
                const int co = wm * 64 + mi * 16 + (lane >> 2) + h * 8;
#pragma unroll
                for (int ni = 0; ni < 4; ni++) {
                    const int px = wn * 32 + ni * 8 + (lane & 3) * 2;
                    sAcc[co * 132 + px]     = acc[mi][ni][h * 2];
                    sAcc[co * 132 + px + 1] = acc[mi][ni][h * 2 + 1];
                }
            }
        __syncthreads();
#pragma unroll
        for (int it = 0; it < 8; it++) {
            const int t2 = it * 256 + tid;
            const int co = t2 >> 4;
            const int ch = t2 & 15;
            const int j  = ch >> 3;
            const int xl = (ch & 7) * 8;
            const float* rowp = sAcc + co * 132 + j * 64;
            float4 va = *(const float4*)(rowp + xl);
            float4 vb = *(const float4*)(rowp + xl + 4);
            const int gb = ((b * 256 + co0 + co) << 12) + ((y0 + j) << 6) + xl;
            float4 x0 = *(const float4*)(xres + gb);
            float4 x1 = *(const float4*)(xres + gb + 4);
            float4 r0, r1;
            r0.x = va.x + x0.x; r0.y = va.y + x0.y;
            r0.z = va.z + x0.z; r0.w = va.w + x0.w;
            r1.x = vb.x + x1.x; r1.y = vb.y + x1.y;
            r1.z = vb.z + x1.z; r1.w = vb.w + x1.w;
            *(float4*)(out + gb)     = r0;
            *(float4*)(out + gb + 4) = r1;
        }
    }
}

// ------------------------------- launcher ----------------------------------
extern "C" void kernel_launch(void* const* d_in, const int* in_sizes, int n_in,
                              void* d_out, int out_size)
{
    const float* x    = (const float*)d_in[0];
    const float* h_in = (const float*)d_in[1];
    const float* g1   = (const float*)d_in[2];
    const float* be1  = (const float*)d_in[3];
    const float* m1   = (const float*)d_in[4];
    const float* v1   = (const float*)d_in[5];
    const float* w1   = (const float*)d_in[6];
    const float* b1   = (const float*)d_in[7];
    const float* g2   = (const float*)d_in[8];
    const float* be2  = (const float*)d_in[9];
    const float* m2   = (const float*)d_in[10];
    const float* v2   = (const float*)d_in[11];
    const float* w2   = (const float*)d_in[12];
    const float* b2   = (const float*)d_in[13];
    float* out = (float*)d_out;

    void *p1, *p2, *pg1, *pg2;
    cudaGetSymbolAddress(&p1, g_at1);
    cudaGetSymbolAddress(&p2, g_at2);
    cudaGetSymbolAddress(&pg1, g_gw1);
    cudaGetSymbolAddress(&pg2, g_gw2);
    __half* at1 = (__half*)p1;
    __half* at2 = (__half*)p2;
    __half* gw1 = (__half*)pg1;
    __half* gw2 = (__half*)pg2;

    cudaFuncSetAttribute(conv_mma<0>, cudaFuncAttributeMaxDynamicSharedMemorySize, SMEM_BYTES);
    cudaFuncSetAttribute(conv_mma<1>, cudaFuncAttributeMaxDynamicSharedMemorySize, SMEM_BYTES);

    aux_fused<<<WGEN_BLKS + BNT_BLKS + ZB_BLKS, 256>>>(
        w1, b1, h_in, gw1,
        x, g1, be1, m1, v1, at1, at2);

    dim3 cg(32, 2, NB);
    cudaLaunchAttribute attrs[1];
    attrs[0].id = cudaLaunchAttributeProgrammaticStreamSerialization;
    attrs[0].val.programmaticStreamSerializationAllowed = 1;

    cudaLaunchConfig_t cfg1 = {};
    cfg1.gridDim = cg;
    cfg1.blockDim = dim3(256, 1, 1);
    cfg1.dynamicSmemBytes = SMEM_BYTES;
    cfg1.stream = 0;
    cfg1.attrs = attrs;
    cfg1.numAttrs = 1;
    cudaLaunchKernelEx(&cfg1, conv_mma<0>,
                       (const __half*)at1, (const __half*)gw1,
                       (const float*)g2, (const float*)be2,
                       (const float*)m2, (const float*)v2,
                       (const float*)nullptr, (__half*)at2, (float*)nullptr,
                       (const float*)w2, (const float*)b2,
                       (const float*)h_in, (__half*)gw2);

    cudaLaunchConfig_t cfg2 = {};
    cfg2.gridDim = cg;
    cfg2.blockDim = dim3(256, 1, 1);
    cfg2.dynamicSmemBytes = SMEM_BYTES;
    cfg2.stream = 0;
    cfg2.attrs = attrs;
    cfg2.numAttrs = 1;
    cudaLaunchKernelEx(&cfg2, conv_mma<1>,
                       (const __half*)at2, (const __half*)gw2,
                       (const float*)nullptr, (const float*)nullptr,
                       (const float*)nullptr, (const float*)nullptr,
                       (const float*)x, (__half*)nullptr, (float*)out,
                       (const float*)nullptr, (const float*)nullptr,
                       (const float*)nullptr, (__half*)nullptr);
}